// round 1
// baseline (speedup 1.0000x reference)
#include <cuda_runtime.h>
#include <cuda_bf16.h>

// Multi-level DB4 DWT along rows of a 4096x4096 fp32 matrix.
// Reference does 11 rounds of (dense GEMM with banded wavelet matrix) +
// even/odd deinterleave. We exploit the band structure: each output pair is a
// 4-tap filter. One CTA per row; the whole row lives in shared memory for all
// 11 levels. HBM traffic = one read + one write of the matrix (128 MB total).
//
// Boundary semantics (derived from build_matrix + the [:L,:L] slicing):
//   level 0 (L == N): last pair wraps around (x[L]->x[0], x[L+1]->x[1])
//   level > 0:        W[:L,:L] truncates the wrap rows -> tail contributions are 0

#define NCOLS    4096
#define NTHREADS 256
#define NLEVELS  11   // log2(4096) - 1
#define MAXK     (NCOLS / 2 / NTHREADS)   // 8 pairs per thread at level 0

__global__ __launch_bounds__(NTHREADS)
void dwt_db4_rows_kernel(const float* __restrict__ in, float* __restrict__ out)
{
    __shared__ float s[NCOLS];

    const int tid = threadIdx.x;
    const int row = blockIdx.x;

    const float c0 =  0.4829629131445341f;
    const float c1 =  0.8365163037378079f;
    const float c2 =  0.2241438680420134f;
    const float c3 = -0.1294095225512604f;

    // ---- load row (coalesced float4) ----
    const float4* __restrict__ gin = (const float4*)(in + (size_t)row * NCOLS);
    float4* s4 = (float4*)s;
    #pragma unroll
    for (int j = 0; j < NCOLS / 4 / NTHREADS; ++j)
        s4[tid + j * NTHREADS] = gin[tid + j * NTHREADS];
    __syncthreads();

    // ---- 11 DWT levels, all in shared memory ----
    #pragma unroll 1
    for (int lvl = 0; lvl < NLEVELS; ++lvl) {
        const int L    = NCOLS >> lvl;
        const int half = L >> 1;

        float a[MAXK], d[MAXK];
        const float2* s2 = (const float2*)s;

        // compute phase: all reads of s happen here, results staged in regs
        #pragma unroll
        for (int j = 0; j < MAXK; ++j) {
            const int k = tid + j * NTHREADS;
            if (k < half) {
                const float2 x01 = s2[k];          // x[2k], x[2k+1]
                float x2, x3;
                if (k + 1 < half) {
                    const float2 x23 = s2[k + 1];  // x[2k+2], x[2k+3]
                    x2 = x23.x; x3 = x23.y;
                } else if (lvl == 0) {
                    x2 = s[0];  x3 = s[1];         // circular wrap at full length
                } else {
                    x2 = 0.0f;  x3 = 0.0f;         // truncated by the [:L,:L] slice
                }
                a[j] = c0 * x01.x + c1 * x01.y + c2 * x2 + c3 * x3;
                d[j] = c3 * x01.x - c2 * x01.y + c1 * x2 - c0 * x3;
            }
        }
        __syncthreads();

        // write-back phase: approx -> s[0:half), detail -> s[half:L)
        #pragma unroll
        for (int j = 0; j < MAXK; ++j) {
            const int k = tid + j * NTHREADS;
            if (k < half) {
                s[k]        = a[j];
                s[half + k] = d[j];
            }
        }
        __syncthreads();
    }

    // ---- store row (coalesced float4) ----
    float4* __restrict__ gout = (float4*)(out + (size_t)row * NCOLS);
    #pragma unroll
    for (int j = 0; j < NCOLS / 4 / NTHREADS; ++j)
        gout[tid + j * NTHREADS] = s4[tid + j * NTHREADS];
}

extern "C" void kernel_launch(void* const* d_in, const int* in_sizes, int n_in,
                              void* d_out, int out_size)
{
    const float* x = (const float*)d_in[0];   // input: (4096, 4096) fp32
    // d_in[1] is W; unused — the DB4 taps are compile-time constants.
    float* out = (float*)d_out;

    dwt_db4_rows_kernel<<<NCOLS, NTHREADS>>>(x, out);
}

// round 2
// speedup vs baseline: 2.1654x; 2.1654x over previous
#include <cuda_runtime.h>
#include <cuda_bf16.h>

// Multi-level DB4 DWT along rows of 4096x4096 fp32.
// Each output pair is a 4-tap filter:
//   a_k = c0 x[2k] + c1 x[2k+1] + c2 x[2k+2] + c3 x[2k+3]
//   d_k = c3 x[2k] - c2 x[2k+1] + c1 x[2k+2] - c0 x[2k+3]
// Level 0 (L==N): last pair wraps to x[0],x[1]. Levels >0: tail truncated to 0
// (the [:L,:L] slice of the transposed band matrix cuts the wrap rows).
//
// One CTA per row, 256 threads.
//  Phase 1: levels 0-1 entirely in registers from the coalesced global load;
//           d0/d1 stored straight to their final global positions; only a1
//           (4KB) goes to SMEM. Warp-boundary neighbors via tiny SMEM arrays.
//  Phase 2: levels 2-4 in SMEM, one float4 read per 2 output pairs, neighbor
//           via shuffle (lane31 via LDS), d's STG'd directly.
//  Phase 3: levels 5-10 in warp 0, registers + shuffles only, direct STG.

#define NCOLS 4096
#define NT    256

__global__ __launch_bounds__(NT)
void dwt_db4_rows_kernel(const float* __restrict__ in, float* __restrict__ out)
{
    __shared__ float sa[2048];   // a-chain workspace (a1 len 1024, then in-place)
    __shared__ float bnd0[64];   // (x0,x1)   of block m for lane-0 threads: idx 2*(warp + 8*j)
    __shared__ float bnd1[64];   // (a0_0,a0_1) likewise

    const int t    = threadIdx.x;
    const int lane = t & 31;
    const int warp = t >> 5;
    const int row  = blockIdx.x;

    const float c0 =  0.4829629131445341f;
    const float c1 =  0.8365163037378079f;
    const float c2 =  0.2241438680420134f;
    const float c3 = -0.1294095225512604f;

    const float4* __restrict__ gin = (const float4*)(in + (size_t)row * NCOLS);
    float* __restrict__ go = out + (size_t)row * NCOLS;

    // ---------------- Phase 1: load + levels 0,1 in registers ----------------
    float4 X[4];
    #pragma unroll
    for (int j = 0; j < 4; ++j)
        X[j] = gin[t + NT * j];

    if (lane == 0) {
        #pragma unroll
        for (int j = 0; j < 4; ++j) {
            bnd0[2 * (warp + 8 * j)]     = X[j].x;
            bnd0[2 * (warp + 8 * j) + 1] = X[j].y;
        }
    }
    __syncthreads();

    float a00[4], a01[4];                 // a0[2m], a0[2m+1] per j-block
    #pragma unroll
    for (int j = 0; j < 4; ++j) {
        const int m = t + NT * j;         // block index: covers x[4m..4m+3]
        // neighbor = first two elements of block m+1
        float n0 = __shfl_down_sync(0xffffffffu, X[j].x, 1);
        float n1 = __shfl_down_sync(0xffffffffu, X[j].y, 1);
        if (lane == 31) {
            const int mb = m + 1;         // 1..1024 ; 1024 -> wraps to block 0 (level-0 wrap)
            const int bi = 2 * (((mb >> 5) & 7) + 8 * ((mb >> 8) & 3));
            n0 = bnd0[bi];
            n1 = bnd0[bi + 1];
        }
        const float aA = c0 * X[j].x + c1 * X[j].y + c2 * X[j].z + c3 * X[j].w;
        const float dA = c3 * X[j].x - c2 * X[j].y + c1 * X[j].z - c0 * X[j].w;
        const float aB = c0 * X[j].z + c1 * X[j].w + c2 * n0 + c3 * n1;
        const float dB = c3 * X[j].z - c2 * X[j].w + c1 * n0 - c0 * n1;
        a00[j] = aA;
        a01[j] = aB;
        // d0 -> final position out[2048 + 2m], out[2048 + 2m + 1]
        ((float2*)go)[1024 + m] = make_float2(dA, dB);
        if (lane == 0) {
            bnd1[2 * (warp + 8 * j)]     = aA;
            bnd1[2 * (warp + 8 * j) + 1] = aB;
        }
    }
    __syncthreads();

    #pragma unroll
    for (int j = 0; j < 4; ++j) {
        const int m = t + NT * j;         // level-1 pair index (0..1023)
        float n0 = __shfl_down_sync(0xffffffffu, a00[j], 1);
        float n1 = __shfl_down_sync(0xffffffffu, a01[j], 1);
        if (lane == 31) {
            const int mb = m + 1;
            if (mb >= 1024) {             // level > 0: truncated, not wrapped
                n0 = 0.0f; n1 = 0.0f;
            } else {
                const int bi = 2 * (((mb >> 5) & 7) + 8 * ((mb >> 8) & 3));
                n0 = bnd1[bi];
                n1 = bnd1[bi + 1];
            }
        }
        const float a = c0 * a00[j] + c1 * a01[j] + c2 * n0 + c3 * n1;
        const float d = c3 * a00[j] - c2 * a01[j] + c1 * n0 - c0 * n1;
        go[1024 + m] = d;                 // final position
        sa[m] = a;                        // a1 -> SMEM
    }
    __syncthreads();

    // ---------------- Phase 2: levels 2,3,4 in SMEM ----------------
    // lvl loop idx l: level 2+l, input length 1024>>l, blocks nb = 256>>l,
    // d output offset 512>>l.
    #pragma unroll 1
    for (int l = 0; l < 3; ++l) {
        const int nb = 256 >> l;
        float4 Y = make_float4(0.f, 0.f, 0.f, 0.f);
        float n0 = 0.f, n1 = 0.f;
        if (t < nb) {
            Y = ((const float4*)sa)[t];   // a[4t..4t+3]
            n0 = __shfl_down_sync(0xffffffffu, Y.x, 1);
            n1 = __shfl_down_sync(0xffffffffu, Y.y, 1);
            if (lane == 31) {
                if (t == nb - 1) { n0 = 0.f; n1 = 0.f; }       // truncation
                else            { n0 = sa[4 * t + 4]; n1 = sa[4 * t + 5]; }
            }
        }
        __syncthreads();                  // all reads of sa done
        if (t < nb) {
            const float aA = c0 * Y.x + c1 * Y.y + c2 * Y.z + c3 * Y.w;
            const float dA = c3 * Y.x - c2 * Y.y + c1 * Y.z - c0 * Y.w;
            const float aB = c0 * Y.z + c1 * Y.w + c2 * n0 + c3 * n1;
            const float dB = c3 * Y.z - c2 * Y.w + c1 * n0 - c0 * n1;
            ((float2*)sa)[t] = make_float2(aA, aB);            // a -> [0, 2*nb)
            ((float2*)(go + (512 >> l)))[t] = make_float2(dA, dB); // final d
        }
        __syncthreads();
    }

    // ---------------- Phase 3: levels 5..10 in warp 0, shuffles only --------
    if (t < 32) {
        // input a4: 128 floats in sa[0..128); lane holds a4[4t..4t+3]
        float4 Y = ((const float4*)sa)[t];

        // level 5 (L=128, half=64): pairs 2t, 2t+1
        float n0 = __shfl_down_sync(0xffffffffu, Y.x, 1);
        float n1 = __shfl_down_sync(0xffffffffu, Y.y, 1);
        if (lane == 31) { n0 = 0.f; n1 = 0.f; }
        const float a5_0 = c0 * Y.x + c1 * Y.y + c2 * Y.z + c3 * Y.w;
        const float d5_0 = c3 * Y.x - c2 * Y.y + c1 * Y.z - c0 * Y.w;
        const float a5_1 = c0 * Y.z + c1 * Y.w + c2 * n0 + c3 * n1;
        const float d5_1 = c3 * Y.z - c2 * Y.w + c1 * n0 - c0 * n1;
        ((float2*)(go + 64))[t] = make_float2(d5_0, d5_1);

        // level 6 (L=64, half=32): lane holds (a5[2t], a5[2t+1])
        n0 = __shfl_down_sync(0xffffffffu, a5_0, 1);
        n1 = __shfl_down_sync(0xffffffffu, a5_1, 1);
        if (lane == 31) { n0 = 0.f; n1 = 0.f; }
        const float a6 = c0 * a5_0 + c1 * a5_1 + c2 * n0 + c3 * n1;
        const float d6 = c3 * a5_0 - c2 * a5_1 + c1 * n0 - c0 * n1;
        go[32 + t] = d6;

        // levels 7..10: one element per lane, gather by shuffle
        float cur = a6;                   // length 32 in lanes 0..31
        int   len = 32;
        int   off = 16;
        #pragma unroll
        for (int lv = 0; lv < 4; ++lv) {
            float x0 = __shfl_sync(0xffffffffu, cur, (2 * t)     & 31);
            float x1 = __shfl_sync(0xffffffffu, cur, (2 * t + 1) & 31);
            float x2 = __shfl_sync(0xffffffffu, cur, (2 * t + 2) & 31);
            float x3 = __shfl_sync(0xffffffffu, cur, (2 * t + 3) & 31);
            x0 = (2 * t     < len) ? x0 : 0.f;
            x1 = (2 * t + 1 < len) ? x1 : 0.f;
            x2 = (2 * t + 2 < len) ? x2 : 0.f;   // truncation at tail
            x3 = (2 * t + 3 < len) ? x3 : 0.f;
            const float a = c0 * x0 + c1 * x1 + c2 * x2 + c3 * x3;
            const float d = c3 * x0 - c2 * x1 + c1 * x2 - c0 * x3;
            if (t < (len >> 1)) go[off + t] = d;
            cur = a;
            len >>= 1;
            off >>= 1;
        }
        // final approx: a10 (len 2) in lanes 0,1 -> out[0], out[1]
        if (t < 2) go[t] = cur;
    }
}

extern "C" void kernel_launch(void* const* d_in, const int* in_sizes, int n_in,
                              void* d_out, int out_size)
{
    const float* x = (const float*)d_in[0];   // (4096, 4096) fp32
    // d_in[1] (W) unused: DB4 taps are compile-time constants.
    float* out = (float*)d_out;

    dwt_db4_rows_kernel<<<NCOLS, NT>>>(x, out);
}